// round 1
// baseline (speedup 1.0000x reference)
#include <cuda_runtime.h>
#include <cuda_bf16.h>

// Problem dims (fixed by dataset): B=8, T=2048 -> N=16384 tokens, D=512, E=8, H=1024, top_k=2
#define N_TOK   16384
#define D_DIM   512
#define E_EXP   8
#define H_DIM   1024
#define NPAIR   (2 * N_TOK)      // exactly 2 expert assignments per token
#define RBLK    (N_TOK / 8)      // router blocks (8 tokens per 256-thread block)

// ---------------- scratch (static device globals; no runtime allocation) ----------------
__device__ float g_h[(size_t)NPAIR * H_DIM];     // hidden activations per (token,expert) pair  (~134 MB)
__device__ float g_out2[(size_t)NPAIR * D_DIM];  // weighted expert outputs per pair            (~67 MB)
__device__ int   g_tok[NPAIR];                   // token index per pair (expert-segment order)
__device__ float g_w[NPAIR];                     // router weight per pair
__device__ int   g_slot[NPAIR];                  // token n, k -> pair index
__device__ int   g_topi[NPAIR];                  // top-2 expert indices per token
__device__ float g_topw[NPAIR];                  // top-2 probs per token
__device__ int   g_cnt[E_EXP];
__device__ int   g_cnt2[E_EXP];
__device__ int   g_off[E_EXP];
__device__ float g_psums[RBLK * E_EXP];          // per-block router prob partial sums

// ---------------- init (must reset counters every graph replay) ----------------
__global__ void init_kernel() {
    int t = threadIdx.x;
    if (t < E_EXP) { g_cnt[t] = 0; g_cnt2[t] = 0; }
}

// ---------------- router: logits, softmax, top-2, counts, prob partial sums ----------------
__global__ void router_kernel(const float* __restrict__ x,
                              const float* __restrict__ Wr,
                              const float* __restrict__ br) {
    __shared__ float ps[8][E_EXP];
    const int wid = threadIdx.x >> 5, lane = threadIdx.x & 31;
    const int n = blockIdx.x * 8 + wid;
    const float* xr = x + (size_t)n * D_DIM;

    float acc[E_EXP];
#pragma unroll
    for (int e = 0; e < E_EXP; e++) acc[e] = 0.f;
    for (int i = lane; i < D_DIM; i += 32) {
        float xv = xr[i];
        const float* w = Wr + i * E_EXP;
#pragma unroll
        for (int e = 0; e < E_EXP; e++) acc[e] += xv * w[e];
    }
#pragma unroll
    for (int e = 0; e < E_EXP; e++) {
#pragma unroll
        for (int o = 16; o > 0; o >>= 1)
            acc[e] += __shfl_xor_sync(0xffffffffu, acc[e], o);
    }

    if (lane == 0) {
        float mx = -1e30f;
#pragma unroll
        for (int e = 0; e < E_EXP; e++) { acc[e] += br[e]; mx = fmaxf(mx, acc[e]); }
        float s = 0.f;
#pragma unroll
        for (int e = 0; e < E_EXP; e++) { acc[e] = expf(acc[e] - mx); s += acc[e]; }
        const float inv = 1.f / s;
        float p1 = -1.f, p2 = -1.f; int i1 = 0, i2 = 0;
#pragma unroll
        for (int e = 0; e < E_EXP; e++) {
            float p = acc[e] * inv;
            ps[wid][e] = p;
            if (p > p1)      { p2 = p1; i2 = i1; p1 = p; i1 = e; }
            else if (p > p2) { p2 = p; i2 = e; }
        }
        g_topi[2 * n]     = i1; g_topw[2 * n]     = p1;
        g_topi[2 * n + 1] = i2; g_topw[2 * n + 1] = p2;
        atomicAdd(&g_cnt[i1], 1);
        atomicAdd(&g_cnt[i2], 1);
    }
    __syncthreads();
    if (threadIdx.x < E_EXP) {   // deterministic per-block reduction
        float s = 0.f;
#pragma unroll
        for (int w = 0; w < 8; w++) s += ps[w][threadIdx.x];
        g_psums[blockIdx.x * E_EXP + threadIdx.x] = s;
    }
}

// ---------------- offsets prefix-sum + gating loss (deterministic order) ----------------
__global__ void offsets_loss_kernel(float* __restrict__ out, int out_size) {
    __shared__ float dsq[E_EXP];
    const int tid = threadIdx.x;
    if (tid == 0) {
        int o = 0;
        for (int e = 0; e < E_EXP; e++) { g_off[e] = o; o += g_cnt[e]; }
    }
    const int wid = tid >> 5, lane = tid & 31;
    if (wid < E_EXP) {   // one warp per expert, fixed summation order
        float s = 0.f;
        for (int b = lane; b < RBLK; b += 32) s += g_psums[b * E_EXP + wid];
#pragma unroll
        for (int o = 16; o > 0; o >>= 1) s += __shfl_xor_sync(0xffffffffu, s, o);
        if (lane == 0) {
            float mean = s / (float)N_TOK;
            float d = (1.0f / E_EXP) - mean;
            dsq[wid] = d * d;
        }
    }
    __syncthreads();
    if (tid == 0 && out_size > N_TOK * D_DIM) {
        float l = 0.f;
        for (int e = 0; e < E_EXP; e++) l += dsq[e];
        out[N_TOK * D_DIM] = (l / E_EXP) * 1e-4f;
    }
}

// ---------------- scatter token assignments into expert segments ----------------
__global__ void scatter_kernel() {
    const int n = blockIdx.x * blockDim.x + threadIdx.x;
    if (n >= N_TOK) return;
#pragma unroll
    for (int k = 0; k < 2; k++) {
        int e = g_topi[2 * n + k];
        int i = atomicAdd(&g_cnt2[e], 1);
        int p = g_off[e] + i;
        g_tok[p] = n;
        g_w[p] = g_topw[2 * n + k];
        g_slot[2 * n + k] = p;
    }
}

// ---------------- fused FFN GEMM (two passes share the skeleton) ----------------
// PASS2=false: h = leaky(X_gathered @ W1[e] + b1[e]),  KDIM=512, NCOL=1024
// PASS2=true : o = w * leaky(H @ W2[e] + b2[e]),       KDIM=1024, NCOL=512
template <bool PASS2, int KDIM, int NCOL>
__global__ void __launch_bounds__(256)
ffn_gemm(const float* __restrict__ x,
         const float* __restrict__ W,
         const float* __restrict__ bias) {
    const int e   = blockIdx.z;
    const int cnt = g_cnt[e];
    const int m0  = blockIdx.y * 128;
    if (m0 >= cnt) return;
    const int n0  = blockIdx.x * 128;
    const int off = g_off[e];

    __shared__ float As[8][128];
    __shared__ float Bs[8][128];
    __shared__ int   toks[128];

    const int tid = threadIdx.x;
    if (!PASS2) {
        if (tid < 128) {
            int m = m0 + tid;
            toks[tid] = (m < cnt) ? g_tok[off + m] : g_tok[off];
        }
        __syncthreads();
    }

    const int la_m = tid >> 1;            // 0..127
    const int la_k = (tid & 1) * 4;       // 0 or 4
    const int lb_k = tid >> 5;            // 0..7
    const int lb_n = (tid & 31) * 4;      // 0..124
    const int tm   = (tid >> 4) * 8;      // 0..120
    const int tn   = (tid & 15) * 8;      // 0..120

    const float* Wb = W + (size_t)e * KDIM * NCOL;
    const float* bb = bias + e * NCOL;

    float acc[8][8];
#pragma unroll
    for (int i = 0; i < 8; i++)
#pragma unroll
        for (int j = 0; j < 8; j++) acc[i][j] = 0.f;

    // A source row for this thread's loads
    size_t arow;
    if (!PASS2) {
        arow = (size_t)toks[la_m] * KDIM;
    } else {
        int m = m0 + la_m;
        int row = (m < cnt) ? (off + m) : off;   // clamp to stay in-bounds
        arow = (size_t)row * KDIM;
    }
    const float* Abase = PASS2 ? g_h : x;

    for (int k0 = 0; k0 < KDIM; k0 += 8) {
        float4 av = *(const float4*)(Abase + arow + k0 + la_k);
        float4 bv = *(const float4*)(Wb + (size_t)(k0 + lb_k) * NCOL + n0 + lb_n);
        As[la_k + 0][la_m] = av.x;
        As[la_k + 1][la_m] = av.y;
        As[la_k + 2][la_m] = av.z;
        As[la_k + 3][la_m] = av.w;
        *(float4*)&Bs[lb_k][lb_n] = bv;
        __syncthreads();
#pragma unroll
        for (int kk = 0; kk < 8; kk++) {
            float a[8], b[8];
#pragma unroll
            for (int i = 0; i < 8; i++) a[i] = As[kk][tm + i];
#pragma unroll
            for (int j = 0; j < 8; j++) b[j] = Bs[kk][tn + j];
#pragma unroll
            for (int i = 0; i < 8; i++)
#pragma unroll
                for (int j = 0; j < 8; j++) acc[i][j] += a[i] * b[j];
        }
        __syncthreads();
    }

#pragma unroll
    for (int i = 0; i < 8; i++) {
        int m = m0 + tm + i;
        if (m >= cnt) break;
        int p = off + m;
        if (!PASS2) {
            float* hrow = g_h + (size_t)p * H_DIM + n0;
#pragma unroll
            for (int j = 0; j < 8; j++) {
                float v = acc[i][j] + bb[n0 + tn + j];
                hrow[tn + j] = (v > 0.f) ? v : 0.01f * v;
            }
        } else {
            float w = g_w[p];
            float* orow = g_out2 + (size_t)p * D_DIM + n0;
#pragma unroll
            for (int j = 0; j < 8; j++) {
                float v = acc[i][j] + bb[n0 + tn + j];
                orow[tn + j] = w * ((v > 0.f) ? v : 0.01f * v);
            }
        }
    }
}

// ---------------- combine: out[n] = out2[slot0] + out2[slot1] ----------------
__global__ void combine_kernel(float* __restrict__ out) {
    const int t = blockIdx.x * blockDim.x + threadIdx.x;
    if (t >= N_TOK * (D_DIM / 4)) return;
    const int n = t / (D_DIM / 4);
    const int d = (t % (D_DIM / 4)) * 4;
    const int s0 = g_slot[2 * n], s1 = g_slot[2 * n + 1];
    float4 a = *(const float4*)(g_out2 + (size_t)s0 * D_DIM + d);
    float4 b = *(const float4*)(g_out2 + (size_t)s1 * D_DIM + d);
    float4 r; r.x = a.x + b.x; r.y = a.y + b.y; r.z = a.z + b.z; r.w = a.w + b.w;
    *(float4*)(out + (size_t)n * D_DIM + d) = r;
}

extern "C" void kernel_launch(void* const* d_in, const int* in_sizes, int n_in,
                              void* d_out, int out_size) {
    const float* x  = (const float*)d_in[0];
    const float* Wr = (const float*)d_in[1];
    const float* br = (const float*)d_in[2];
    const float* W1 = (const float*)d_in[3];
    const float* b1 = (const float*)d_in[4];
    const float* W2 = (const float*)d_in[5];
    const float* b2 = (const float*)d_in[6];
    float* out = (float*)d_out;

    init_kernel<<<1, 32>>>();
    router_kernel<<<RBLK, 256>>>(x, Wr, br);
    offsets_loss_kernel<<<1, 256>>>(out, out_size);
    scatter_kernel<<<(N_TOK + 255) / 256, 256>>>();
    // GEMM1: per-expert gathered X[cnt,512] @ W1[e][512,1024] -> g_h
    ffn_gemm<false, D_DIM, H_DIM><<<dim3(H_DIM / 128, N_TOK / 128, E_EXP), 256>>>(x, W1, b1);
    // GEMM2: g_h[cnt,1024] @ W2[e][1024,512] -> g_out2 (weighted)
    ffn_gemm<true, H_DIM, D_DIM><<<dim3(D_DIM / 128, N_TOK / 128, E_EXP), 256>>>(nullptr, W2, b2);
    combine_kernel<<<(N_TOK * D_DIM / 4 + 255) / 256, 256>>>(out);
}

// round 5
// speedup vs baseline: 2.2998x; 2.2998x over previous
#include <cuda_runtime.h>
#include <cuda_bf16.h>
#include <cstdint>

// Problem dims: B=8, T=2048 -> N=16384 tokens, D=512, E=8, H=1024, top_k=2
#define N_TOK   16384
#define D_DIM   512
#define E_EXP   8
#define H_DIM   1024
#define NPAIR   (2 * N_TOK)
#define RBLK    (N_TOK / 8)

#define BM 128
#define BN 128
#define KCH 64                      // 64 bf16 = 128B of data per row
#define ROWB 144                    // row stride in smem (128B data + 16B pad; 16B aligned)
#define TILE_BYTES (128 * ROWB)     // 18432
#define STAGE_BYTES (4 * TILE_BYTES) // Ah, Al, Bh, Bl = 73728
#define NSTAGE 3
#define SMEM_DYN (1024 + NSTAGE * STAGE_BYTES)   // 222208 < 227KB opt-in max

// ---------------- scratch (static device globals) ----------------
__device__ __align__(1024) __nv_bfloat16 g_xh[(size_t)N_TOK * D_DIM];
__device__ __align__(1024) __nv_bfloat16 g_xl[(size_t)N_TOK * D_DIM];
__device__ __align__(1024) __nv_bfloat16 g_w1h[(size_t)E_EXP * H_DIM * D_DIM]; // [E][H][D] K-major
__device__ __align__(1024) __nv_bfloat16 g_w1l[(size_t)E_EXP * H_DIM * D_DIM];
__device__ __align__(1024) __nv_bfloat16 g_w2h[(size_t)E_EXP * D_DIM * H_DIM]; // [E][D][H] K-major
__device__ __align__(1024) __nv_bfloat16 g_w2l[(size_t)E_EXP * D_DIM * H_DIM];
__device__ __align__(1024) __nv_bfloat16 g_hh[(size_t)NPAIR * H_DIM];
__device__ __align__(1024) __nv_bfloat16 g_hl[(size_t)NPAIR * H_DIM];
__device__ __align__(1024) float g_out2[(size_t)NPAIR * D_DIM];
__device__ int   g_tok[NPAIR];
__device__ float g_w[NPAIR];
__device__ int   g_slot[NPAIR];
__device__ int   g_topi[NPAIR];
__device__ float g_topw[NPAIR];
__device__ int   g_cnt[E_EXP];
__device__ int   g_cnt2[E_EXP];
__device__ int   g_off[E_EXP];
__device__ float g_psums[RBLK * E_EXP];

// ---------------- PTX helpers (baseline ISA only) ----------------
__device__ __forceinline__ uint32_t smem_u32(const void* p) {
    uint32_t a;
    asm("{ .reg .u64 t; cvta.to.shared.u64 t, %1; cvt.u32.u64 %0, t; }" : "=r"(a) : "l"(p));
    return a;
}
__device__ __forceinline__ void cp16(uint32_t dst, const void* src) {
    asm volatile("cp.async.cg.shared.global [%0], [%1], 16;" :: "r"(dst), "l"(src));
}
__device__ __forceinline__ uint32_t lds32(uint32_t addr) {
    uint32_t v;
    asm volatile("ld.shared.b32 %0, [%1];" : "=r"(v) : "r"(addr));
    return v;
}
__device__ __forceinline__ void mma_bf16(float* c, const uint32_t* a, uint32_t b0, uint32_t b1) {
    asm volatile(
        "mma.sync.aligned.m16n8k16.row.col.f32.bf16.bf16.f32 "
        "{%0,%1,%2,%3}, {%4,%5,%6,%7}, {%8,%9}, {%0,%1,%2,%3};"
        : "+f"(c[0]), "+f"(c[1]), "+f"(c[2]), "+f"(c[3])
        : "r"(a[0]), "r"(a[1]), "r"(a[2]), "r"(a[3]), "r"(b0), "r"(b1));
}

// ---------------- init ----------------
__global__ void init_kernel() {
    int t = threadIdx.x;
    if (t < E_EXP) { g_cnt[t] = 0; g_cnt2[t] = 0; }
}

// ---------------- router ----------------
__global__ void router_kernel(const float* __restrict__ x,
                              const float* __restrict__ Wr,
                              const float* __restrict__ br) {
    __shared__ float ps[8][E_EXP];
    const int wid = threadIdx.x >> 5, lane = threadIdx.x & 31;
    const int n = blockIdx.x * 8 + wid;
    const float* xr = x + (size_t)n * D_DIM;
    float acc[E_EXP];
#pragma unroll
    for (int e = 0; e < E_EXP; e++) acc[e] = 0.f;
    for (int i = lane; i < D_DIM; i += 32) {
        float xv = xr[i];
        const float* w = Wr + i * E_EXP;
#pragma unroll
        for (int e = 0; e < E_EXP; e++) acc[e] += xv * w[e];
    }
#pragma unroll
    for (int e = 0; e < E_EXP; e++)
#pragma unroll
        for (int o = 16; o > 0; o >>= 1)
            acc[e] += __shfl_xor_sync(0xffffffffu, acc[e], o);

    if (lane == 0) {
        float mx = -1e30f;
#pragma unroll
        for (int e = 0; e < E_EXP; e++) { acc[e] += br[e]; mx = fmaxf(mx, acc[e]); }
        float s = 0.f;
#pragma unroll
        for (int e = 0; e < E_EXP; e++) { acc[e] = expf(acc[e] - mx); s += acc[e]; }
        const float inv = 1.f / s;
        float p1 = -1.f, p2 = -1.f; int i1 = 0, i2 = 0;
#pragma unroll
        for (int e = 0; e < E_EXP; e++) {
            float p = acc[e] * inv;
            ps[wid][e] = p;
            if (p > p1)      { p2 = p1; i2 = i1; p1 = p; i1 = e; }
            else if (p > p2) { p2 = p; i2 = e; }
        }
        g_topi[2 * n] = i1;     g_topw[2 * n] = p1;
        g_topi[2 * n + 1] = i2; g_topw[2 * n + 1] = p2;
        atomicAdd(&g_cnt[i1], 1);
        atomicAdd(&g_cnt[i2], 1);
    }
    __syncthreads();
    if (threadIdx.x < E_EXP) {
        float s = 0.f;
#pragma unroll
        for (int w = 0; w < 8; w++) s += ps[w][threadIdx.x];
        g_psums[blockIdx.x * E_EXP + threadIdx.x] = s;
    }
}

// ---------------- offsets + gating loss ----------------
__global__ void offsets_loss_kernel(float* __restrict__ out, int out_size) {
    __shared__ float dsq[E_EXP];
    const int tid = threadIdx.x;
    if (tid == 0) {
        int o = 0;
        for (int e = 0; e < E_EXP; e++) { g_off[e] = o; o += g_cnt[e]; }
    }
    const int wid = tid >> 5, lane = tid & 31;
    if (wid < E_EXP) {
        float s = 0.f;
        for (int b = lane; b < RBLK; b += 32) s += g_psums[b * E_EXP + wid];
#pragma unroll
        for (int o = 16; o > 0; o >>= 1) s += __shfl_xor_sync(0xffffffffu, s, o);
        if (lane == 0) {
            float mean = s / (float)N_TOK;
            float d = (1.0f / E_EXP) - mean;
            dsq[wid] = d * d;
        }
    }
    __syncthreads();
    if (tid == 0 && out_size > N_TOK * D_DIM) {
        float l = 0.f;
        for (int e = 0; e < E_EXP; e++) l += dsq[e];
        out[N_TOK * D_DIM] = (l / E_EXP) * 1e-4f;
    }
}

// ---------------- scatter ----------------
__global__ void scatter_kernel() {
    const int n = blockIdx.x * blockDim.x + threadIdx.x;
    if (n >= N_TOK) return;
#pragma unroll
    for (int k = 0; k < 2; k++) {
        int e = g_topi[2 * n + k];
        int i = atomicAdd(&g_cnt2[e], 1);
        int p = g_off[e] + i;
        g_tok[p] = n;
        g_w[p] = g_topw[2 * n + k];
        g_slot[2 * n + k] = p;
    }
}

// ---------------- x -> bf16 hi/lo ----------------
__global__ void convert_x_kernel(const float* __restrict__ x) {
    const int i = blockIdx.x * blockDim.x + threadIdx.x;
    if (i >= N_TOK * D_DIM / 4) return;
    float4 v = ((const float4*)x)[i];
    float vv[4] = {v.x, v.y, v.z, v.w};
    unsigned short hs[4], ls[4];
#pragma unroll
    for (int j = 0; j < 4; j++) {
        __nv_bfloat16 h = __float2bfloat16(vv[j]);
        __nv_bfloat16 l = __float2bfloat16(vv[j] - __bfloat162float(h));
        hs[j] = __bfloat16_as_ushort(h);
        ls[j] = __bfloat16_as_ushort(l);
    }
    ((uint2*)g_xh)[i] = make_uint2((uint32_t)hs[0] | ((uint32_t)hs[1] << 16),
                                   (uint32_t)hs[2] | ((uint32_t)hs[3] << 16));
    ((uint2*)g_xl)[i] = make_uint2((uint32_t)ls[0] | ((uint32_t)ls[1] << 16),
                                   (uint32_t)ls[2] | ((uint32_t)ls[3] << 16));
}

// ---------------- weight transpose + split: [E][K][N] fp32 -> [E][N][K] bf16 hi/lo ----------------
// Th/Tl MUST be real device addresses (cudaGetSymbolAddress) — passing the __device__
// symbol directly from host gives the host shadow address (silently writable via ATS on GB300!).
template <int K, int N>
__global__ void transpose_split_kernel(const float* __restrict__ W,
                                       __nv_bfloat16* __restrict__ Th,
                                       __nv_bfloat16* __restrict__ Tl) {
    __shared__ float t[32][33];
    const int e = blockIdx.z;
    const int n0 = blockIdx.x * 32, k0 = blockIdx.y * 32;
    const int tx = threadIdx.x, ty = threadIdx.y;
    for (int i = ty; i < 32; i += 8)
        t[i][tx] = W[((size_t)e * K + k0 + i) * N + n0 + tx];
    __syncthreads();
    for (int i = ty; i < 32; i += 8) {
        float v = t[tx][i];                       // = in[k0+tx][n0+i]
        __nv_bfloat16 h = __float2bfloat16(v);
        __nv_bfloat16 l = __float2bfloat16(v - __bfloat162float(h));
        size_t o = ((size_t)e * N + n0 + i) * K + k0 + tx;
        Th[o] = h;
        Tl[o] = l;
    }
}

// ---------------- HMMA GEMM via mma.sync; plain (non-swizzled) smem, explicit LDS fragments ----
// PASS2=false: h = leaky(gather(x) @ W1t^T + b1) -> g_hh/g_hl,  KDIM=512,  NCOL=1024
// PASS2=true : o = w * leaky(h @ W2t^T + b2)     -> g_out2,     KDIM=1024, NCOL=512
template <bool PASS2, int KDIM, int NCOL>
__global__ void __launch_bounds__(256, 1)
gemm_mma(const float* __restrict__ bias) {
    extern __shared__ char smem[];
    const int e = blockIdx.z;
    const int cnt = g_cnt[e];
    const int m0 = blockIdx.y * BM;
    if (m0 >= cnt) return;
    const int n0 = blockIdx.x * BN;
    const int off = g_off[e];
    const int tid = threadIdx.x;
    const int wid = tid >> 5, lane = tid & 31;
    const int warp_m = wid >> 2;                 // 0..1 (64 rows each)
    const int warp_n = wid & 3;                  // 0..3 (32 cols each)
    const int qr = lane >> 2;                    // 0..7
    const int qc = (lane & 3) * 2;               // 0,2,4,6  (k element pair base)

    const uint32_t sbase = smem_u32(smem);
    int* toks = (int*)smem;                      // [0,512)
    const uint32_t TILE0 = 1024;

    if (!PASS2) {
        if (tid < BM) {
            int m = m0 + tid;
            toks[tid] = g_tok[off + (m < cnt ? m : cnt - 1)];
        }
        __syncthreads();
    }

    const char* Ahb = (const char*)(PASS2 ? g_hh  : g_xh);   // device-side symbol refs: real addrs
    const char* Alb = (const char*)(PASS2 ? g_hl  : g_xl);
    const char* Bhb = (const char*)(PASS2 ? g_w2h : g_w1h);
    const char* Blb = (const char*)(PASS2 ? g_w2l : g_w1l);

    // cp.async plan: 4 units of 16B per tile type (128 rows x 8 units of 16B data)
    size_t aoff[4], boff[4];
    uint32_t dst[4];
#pragma unroll
    for (int t = 0; t < 4; t++) {
        int uu = tid + 256 * t;
        int r = uu >> 3, u = uu & 7;
        dst[t] = (uint32_t)(r * ROWB + u * 16);   // plain layout, padded rows
        if (!PASS2) {
            aoff[t] = ((size_t)toks[r] * KDIM) * 2 + u * 16;
        } else {
            int m = m0 + r;
            int row = off + (m < cnt ? m : cnt - 1);
            aoff[t] = ((size_t)row * KDIM) * 2 + u * 16;
        }
        boff[t] = ((size_t)(e * NCOL + n0 + r) * KDIM) * 2 + u * 16;
    }

    auto issue_loads = [&](int c, int s) {
        const uint32_t st = sbase + TILE0 + s * STAGE_BYTES;
        const size_t kb = (size_t)c * (KCH * 2);
#pragma unroll
        for (int t = 0; t < 4; t++) {
            cp16(st + dst[t],                  Ahb + aoff[t] + kb);
            cp16(st + TILE_BYTES + dst[t],     Alb + aoff[t] + kb);
            cp16(st + 2 * TILE_BYTES + dst[t], Bhb + boff[t] + kb);
            cp16(st + 3 * TILE_BYTES + dst[t], Blb + boff[t] + kb);
        }
        asm volatile("cp.async.commit_group;" ::: "memory");
    };

    float acc[4][4][4];
#pragma unroll
    for (int f = 0; f < 4; f++)
#pragma unroll
        for (int g = 0; g < 4; g++)
#pragma unroll
            for (int q = 0; q < 4; q++) acc[f][g][q] = 0.f;

    constexpr int C = KDIM / KCH;
    issue_loads(0, 0);
    issue_loads(1, 1);

    // fragment base addresses (relative to tile start)
    uint32_t aRow[4], bRow[4];
#pragma unroll
    for (int f = 0; f < 4; f++) aRow[f] = (uint32_t)((warp_m * 64 + f * 16 + qr) * ROWB);
#pragma unroll
    for (int g = 0; g < 4; g++) bRow[g] = (uint32_t)((warp_n * 32 + g * 8 + qr) * ROWB);

    for (int c = 0; c < C; c++) {
        const int s = c % NSTAGE;
        if (c == C - 1) asm volatile("cp.async.wait_group 0;" ::: "memory");
        else            asm volatile("cp.async.wait_group 1;" ::: "memory");
        __syncthreads();
        if (c + 2 < C) issue_loads(c + 2, (c + 2) % NSTAGE);

        const uint32_t stAh = sbase + TILE0 + s * STAGE_BYTES;
        const uint32_t stAl = stAh + TILE_BYTES;
        const uint32_t stBh = stAh + 2 * TILE_BYTES;
        const uint32_t stBl = stAh + 3 * TILE_BYTES;

#pragma unroll
        for (int ks = 0; ks < 4; ks++) {
            // byte offsets within a row for this k16 step
            const uint32_t kb0 = (uint32_t)((ks * 16 + qc) * 2);      // k 0-7 half
            const uint32_t kb1 = kb0 + 16;                             // k 8-15 half
            uint32_t ah[4][4], al[4][4], bh[4][2], bl[4][2];
#pragma unroll
            for (int f = 0; f < 4; f++) {
                ah[f][0] = lds32(stAh + aRow[f] + kb0);
                ah[f][1] = lds32(stAh + aRow[f] + 8 * ROWB + kb0);
                ah[f][2] = lds32(stAh + aRow[f] + kb1);
                ah[f][3] = lds32(stAh + aRow[f] + 8 * ROWB + kb1);
                al[f][0] = lds32(stAl + aRow[f] + kb0);
                al[f][1] = lds32(stAl + aRow[f] + 8 * ROWB + kb0);
                al[f][2] = lds32(stAl + aRow[f] + kb1);
                al[f][3] = lds32(stAl + aRow[f] + 8 * ROWB + kb1);
            }
#pragma unroll
            for (int g = 0; g < 4; g++) {
                bh[g][0] = lds32(stBh + bRow[g] + kb0);
                bh[g][1] = lds32(stBh + bRow[g] + kb1);
                bl[g][0] = lds32(stBl + bRow[g] + kb0);
                bl[g][1] = lds32(stBl + bRow[g] + kb1);
            }
#pragma unroll
            for (int f = 0; f < 4; f++)
#pragma unroll
                for (int g = 0; g < 4; g++) {
                    mma_bf16(acc[f][g], ah[f], bh[g][0], bh[g][1]);
                    mma_bf16(acc[f][g], al[f], bh[g][0], bh[g][1]);
                    mma_bf16(acc[f][g], ah[f], bl[g][0], bl[g][1]);
                }
        }
        __syncthreads();
    }

    // ---- epilogue: fp32 C frags -> bias + leaky (+wgt / hi-lo split), direct stores ----
    const float* bb = bias + e * NCOL + n0;
#pragma unroll
    for (int f = 0; f < 4; f++) {
        const int rbase = warp_m * 64 + f * 16 + qr;
#pragma unroll
        for (int half = 0; half < 2; half++) {
            const int row = rbase + half * 8;
            const int m = m0 + row;
            if (m >= cnt) continue;
            const int grow = off + m;
            float wgt = 0.f;
            if (PASS2) wgt = g_w[grow];
#pragma unroll
            for (int g = 0; g < 4; g++) {
                const int col = warp_n * 32 + g * 8 + qc;
                float v0 = acc[f][g][2 * half + 0] + bb[col];
                float v1 = acc[f][g][2 * half + 1] + bb[col + 1];
                v0 = (v0 > 0.f) ? v0 : 0.01f * v0;
                v1 = (v1 > 0.f) ? v1 : 0.01f * v1;
                const size_t base = (size_t)grow * NCOL + n0 + col;
                if (!PASS2) {
                    __nv_bfloat16 h0 = __float2bfloat16(v0);
                    __nv_bfloat16 l0 = __float2bfloat16(v0 - __bfloat162float(h0));
                    __nv_bfloat16 h1 = __float2bfloat16(v1);
                    __nv_bfloat16 l1 = __float2bfloat16(v1 - __bfloat162float(h1));
                    *(uint32_t*)&g_hh[base] =
                        (uint32_t)__bfloat16_as_ushort(h0) | ((uint32_t)__bfloat16_as_ushort(h1) << 16);
                    *(uint32_t*)&g_hl[base] =
                        (uint32_t)__bfloat16_as_ushort(l0) | ((uint32_t)__bfloat16_as_ushort(l1) << 16);
                } else {
                    *(float2*)&g_out2[base] = make_float2(wgt * v0, wgt * v1);
                }
            }
        }
    }
}

// ---------------- combine ----------------
__global__ void combine_kernel(float* __restrict__ out) {
    const int t = blockIdx.x * blockDim.x + threadIdx.x;
    if (t >= N_TOK * (D_DIM / 4)) return;
    const int n = t / (D_DIM / 4);
    const int d = (t % (D_DIM / 4)) * 4;
    const int s0 = g_slot[2 * n], s1 = g_slot[2 * n + 1];
    float4 a = *(const float4*)(g_out2 + (size_t)s0 * D_DIM + d);
    float4 b = *(const float4*)(g_out2 + (size_t)s1 * D_DIM + d);
    float4 r; r.x = a.x + b.x; r.y = a.y + b.y; r.z = a.z + b.z; r.w = a.w + b.w;
    *(float4*)(out + (size_t)n * D_DIM + d) = r;
}

extern "C" void kernel_launch(void* const* d_in, const int* in_sizes, int n_in,
                              void* d_out, int out_size) {
    const float* x  = (const float*)d_in[0];
    const float* Wr = (const float*)d_in[1];
    const float* br = (const float*)d_in[2];
    const float* W1 = (const float*)d_in[3];
    const float* b1 = (const float*)d_in[4];
    const float* W2 = (const float*)d_in[5];
    const float* b2 = (const float*)d_in[6];
    float* out = (float*)d_out;

    cudaFuncSetAttribute(gemm_mma<false, D_DIM, H_DIM>,
                         cudaFuncAttributeMaxDynamicSharedMemorySize, SMEM_DYN);
    cudaFuncSetAttribute(gemm_mma<true, H_DIM, D_DIM>,
                         cudaFuncAttributeMaxDynamicSharedMemorySize, SMEM_DYN);

    // REAL device addresses of the __device__ scratch symbols (NOT the host shadows!)
    __nv_bfloat16 *w1h, *w1l, *w2h, *w2l;
    cudaGetSymbolAddress((void**)&w1h, g_w1h);
    cudaGetSymbolAddress((void**)&w1l, g_w1l);
    cudaGetSymbolAddress((void**)&w2h, g_w2h);
    cudaGetSymbolAddress((void**)&w2l, g_w2l);

    init_kernel<<<1, 32>>>();
    router_kernel<<<RBLK, 256>>>(x, Wr, br);
    offsets_loss_kernel<<<1, 256>>>(out, out_size);
    scatter_kernel<<<(N_TOK + 255) / 256, 256>>>();
    convert_x_kernel<<<(N_TOK * D_DIM / 4 + 255) / 256, 256>>>(x);
    transpose_split_kernel<D_DIM, H_DIM><<<dim3(H_DIM / 32, D_DIM / 32, E_EXP), dim3(32, 8)>>>(W1, w1h, w1l);
    transpose_split_kernel<H_DIM, D_DIM><<<dim3(D_DIM / 32, H_DIM / 32, E_EXP), dim3(32, 8)>>>(W2, w2h, w2l);

    gemm_mma<false, D_DIM, H_DIM>
        <<<dim3(H_DIM / BN, N_TOK / BM, E_EXP), 256, SMEM_DYN>>>(b1);
    gemm_mma<true, H_DIM, D_DIM>
        <<<dim3(D_DIM / BN, N_TOK / BM, E_EXP), 256, SMEM_DYN>>>(b2);
    combine_kernel<<<(N_TOK * D_DIM / 4 + 255) / 256, 256>>>(out);
}